// round 1
// baseline (speedup 1.0000x reference)
#include <cuda_runtime.h>
#include <math.h>

#define BB 512
#define SS 64
#define TT 32
#define VV 128
#define EE 256
#define HH 512
#define DENC 1024
#define G4H 2048
#define EOS_IDX 2

// ---------------- scratch (device globals; no allocations) ----------------
__device__ float g_enc_proj[(size_t)BB * SS * HH];     // 64 MB
__device__ float g_xemb[(size_t)BB * TT * EE];         // 16 MB
__device__ float g_gates_emb[(size_t)BB * TT * G4H];   // 128 MB
__device__ float g_Wc0[G4H * (DENC + HH)];             // [W_ih0[:,E:] | W_hh0]
__device__ float g_Wc1[G4H * (HH + HH)];               // [W_ih1 | W_hh1]
__device__ float g_xbuf[BB * (DENC + HH)];             // [context | h0]
__device__ float g_x1buf[BB * (HH + HH)];              // [h0n | h1]
__device__ float g_x2buf[BB * (HH + DENC)];            // [h1n | context]
__device__ float g_gates[BB * G4H];
__device__ float g_c0buf[BB * HH];
__device__ float g_c1buf[BB * HH];
__device__ float g_decproj[BB * HH];

__device__ __forceinline__ float sigmoidf_(float x) { return 1.0f / (1.0f + expf(-x)); }

// ---------------- generic fp32 NT GEMM: C[M,N] = A(MxK) * B(NxK)^T ----------------
// Optional: + bias0[n] + bias1[n] + Cin[m,n]; optional accumulate into existing C.
template <int BM, int BN, int BK, int TM, int TN>
__global__ void __launch_bounds__((BM / TM) * (BN / TN))
sgemm_nt_kernel(int M, int N, int K,
                const float* __restrict__ A, int lda,
                const float* __restrict__ B, int ldb,
                float* __restrict__ C, int ldc,
                const float* __restrict__ Cin, int ldcin,
                const float* __restrict__ bias0,
                const float* __restrict__ bias1,
                int accumulate) {
    constexpr int THREADS = (BM / TM) * (BN / TN);
    __shared__ float As[BK][BM];
    __shared__ float Bs[BK][BN];

    const int tid = threadIdx.x;
    const int bm = blockIdx.y * BM;
    const int bn = blockIdx.x * BN;

    const int tRow = tid / (BK / 4);
    const int tCol = (tid % (BK / 4)) * 4;
    constexpr int ROWS_PER_PASS = THREADS / (BK / 4);

    const int tx = tid % (BN / TN);
    const int ty = tid / (BN / TN);

    float acc[TM][TN];
#pragma unroll
    for (int i = 0; i < TM; i++)
#pragma unroll
        for (int j = 0; j < TN; j++) acc[i][j] = 0.0f;

    for (int k0 = 0; k0 < K; k0 += BK) {
#pragma unroll
        for (int i = 0; i < BM; i += ROWS_PER_PASS) {
            float4 va = *(const float4*)(A + (size_t)(bm + i + tRow) * lda + k0 + tCol);
            As[tCol + 0][i + tRow] = va.x;
            As[tCol + 1][i + tRow] = va.y;
            As[tCol + 2][i + tRow] = va.z;
            As[tCol + 3][i + tRow] = va.w;
        }
#pragma unroll
        for (int i = 0; i < BN; i += ROWS_PER_PASS) {
            float4 vb = *(const float4*)(B + (size_t)(bn + i + tRow) * ldb + k0 + tCol);
            Bs[tCol + 0][i + tRow] = vb.x;
            Bs[tCol + 1][i + tRow] = vb.y;
            Bs[tCol + 2][i + tRow] = vb.z;
            Bs[tCol + 3][i + tRow] = vb.w;
        }
        __syncthreads();
#pragma unroll
        for (int k = 0; k < BK; k++) {
            float ra[TM], rb[TN];
#pragma unroll
            for (int i = 0; i < TM; i++) ra[i] = As[k][ty * TM + i];
#pragma unroll
            for (int j = 0; j < TN; j++) rb[j] = Bs[k][tx * TN + j];
#pragma unroll
            for (int i = 0; i < TM; i++)
#pragma unroll
                for (int j = 0; j < TN; j++) acc[i][j] = fmaf(ra[i], rb[j], acc[i][j]);
        }
        __syncthreads();
    }

#pragma unroll
    for (int i = 0; i < TM; i++) {
        const int row = bm + ty * TM + i;
#pragma unroll
        for (int j = 0; j < TN; j++) {
            const int col = bn + tx * TN + j;
            float v = acc[i][j];
            if (bias0) v += bias0[col];
            if (bias1) v += bias1[col];
            if (Cin) v += Cin[(size_t)row * ldcin + col];
            if (accumulate) v += C[(size_t)row * ldc + col];
            C[(size_t)row * ldc + col] = v;
        }
    }
}

template <int BM, int BN, int BK, int TM, int TN>
static void gemm(int M, int N, int K,
                 const float* A, int lda, const float* B, int ldb,
                 float* C, int ldc,
                 const float* Cin = nullptr, int ldcin = 0,
                 const float* bias0 = nullptr, const float* bias1 = nullptr,
                 bool accumulate = false) {
    dim3 grid(N / BN, M / BM);
    sgemm_nt_kernel<BM, BN, BK, TM, TN><<<grid, (BM / TM) * (BN / TN)>>>(
        M, N, K, A, lda, B, ldb, C, ldc, Cin, ldcin, bias0, bias1, accumulate ? 1 : 0);
}

// ---------------- precompute kernels ----------------
__global__ void embed_kernel(const int* __restrict__ targets,
                             const float* __restrict__ emb,
                             float* __restrict__ xemb) {
    int idx = blockIdx.x * blockDim.x + threadIdx.x;  // B*T*E
    int e = idx & (EE - 1);
    int m = idx >> 8;        // b*T + t
    int t = m & (TT - 1);
    int b = m >> 5;
    int tok = (t == 0) ? EOS_IDX : targets[b * TT + t - 1];
    xemb[idx] = emb[(size_t)tok * EE + e];
}

__global__ void build_wcomb_kernel(const float* __restrict__ W_ih0,
                                   const float* __restrict__ W_hh0,
                                   const float* __restrict__ W_ih1,
                                   const float* __restrict__ W_hh1,
                                   float* __restrict__ Wc0,
                                   float* __restrict__ Wc1) {
    int idx = blockIdx.x * blockDim.x + threadIdx.x;
    const int N0 = G4H * (DENC + HH);
    const int N1 = G4H * (HH + HH);
    if (idx < N0) {
        int n = idx / (DENC + HH);
        int k = idx % (DENC + HH);
        Wc0[idx] = (k < DENC) ? W_ih0[(size_t)n * (EE + DENC) + EE + k]
                              : W_hh0[(size_t)n * HH + (k - DENC)];
    } else if (idx < N0 + N1) {
        int r = idx - N0;
        int n = r / (HH + HH);
        int k = r % (HH + HH);
        Wc1[r] = (k < HH) ? W_ih1[(size_t)n * HH + k]
                          : W_hh1[(size_t)n * HH + (k - HH)];
    }
}

__global__ void init_state_kernel(const float* __restrict__ h0,
                                  const float* __restrict__ c0,
                                  float* __restrict__ xbuf,
                                  float* __restrict__ x1buf,
                                  float* __restrict__ cb0,
                                  float* __restrict__ cb1) {
    int idx = blockIdx.x * blockDim.x + threadIdx.x;  // B*H
    int b = idx >> 9;
    int h = idx & (HH - 1);
    xbuf[(size_t)b * (DENC + HH) + DENC + h] = h0[idx];                 // layer 0 h
    x1buf[(size_t)b * (HH + HH) + HH + h] = h0[(size_t)BB * HH + idx];  // layer 1 h
    cb0[idx] = c0[idx];
    cb1[idx] = c0[(size_t)BB * HH + idx];
}

// ---------------- attention (fused score/tanh + masked softmax + context) ----------------
__global__ void __launch_bounds__(256) attention_kernel(
    const float* __restrict__ enc_proj,   // (B,S,H)
    const float* __restrict__ enc,        // (B,S,DENC)
    const float* __restrict__ decp,       // (B,H)
    const float* __restrict__ vvec,       // (H)
    const int* __restrict__ mask,         // (B,S)
    float* __restrict__ ctx_dst1,         // xbuf: col 0, ld DENC+H
    float* __restrict__ ctx_dst2) {       // x2buf: col H, ld H+DENC
    const int b = blockIdx.x;
    __shared__ float s_dp[HH];
    __shared__ float s_v[HH];
    __shared__ float s_w[SS];
    __shared__ float s_red[2];
    const int tid = threadIdx.x;
    const int warp = tid >> 5, lane = tid & 31;

    for (int i = tid; i < HH; i += 256) {
        s_dp[i] = decp[(size_t)b * HH + i];
        s_v[i] = vvec[i];
    }
    __syncthreads();

    for (int s = warp; s < SS; s += 8) {
        const float* ep = enc_proj + ((size_t)b * SS + s) * HH;
        float acc = 0.0f;
        for (int h = lane; h < HH; h += 32)
            acc += s_v[h] * tanhf(s_dp[h] + ep[h]);
#pragma unroll
        for (int o = 16; o; o >>= 1) acc += __shfl_xor_sync(0xffffffffu, acc, o);
        if (lane == 0) s_w[s] = mask[b * SS + s] ? acc : -1e30f;
    }
    __syncthreads();

    if (warp == 0) {
        float m = fmaxf(s_w[lane], s_w[lane + 32]);
#pragma unroll
        for (int o = 16; o; o >>= 1) m = fmaxf(m, __shfl_xor_sync(0xffffffffu, m, o));
        float sum = expf(s_w[lane] - m) + expf(s_w[lane + 32] - m);
#pragma unroll
        for (int o = 16; o; o >>= 1) sum += __shfl_xor_sync(0xffffffffu, sum, o);
        if (lane == 0) { s_red[0] = m; s_red[1] = sum; }
    }
    __syncthreads();
    const float m = s_red[0], inv = 1.0f / s_red[1];
    if (tid < SS) s_w[tid] = expf(s_w[tid] - m) * inv;
    __syncthreads();

    const float* eb = enc + (size_t)b * SS * DENC;
    for (int d = tid; d < DENC; d += 256) {
        float acc = 0.0f;
#pragma unroll 8
        for (int s = 0; s < SS; s++) acc += s_w[s] * eb[(size_t)s * DENC + d];
        ctx_dst1[(size_t)b * (DENC + HH) + d] = acc;
        ctx_dst2[(size_t)b * (HH + DENC) + HH + d] = acc;
    }
}

// ---------------- LSTM pointwise cell ----------------
__global__ void lstm_cell_kernel(const float* __restrict__ gates,  // (B,4H)
                                 float* __restrict__ c,            // (B,H) in/out
                                 float* __restrict__ hA, int ldA,
                                 float* __restrict__ hB, int ldB) {
    int idx = blockIdx.x * blockDim.x + threadIdx.x;  // B*H
    int b = idx >> 9;
    int h = idx & (HH - 1);
    const float* g = gates + (size_t)b * G4H;
    float ig = sigmoidf_(g[h]);
    float fg = sigmoidf_(g[HH + h]);
    float gg = tanhf(g[2 * HH + h]);
    float og = sigmoidf_(g[3 * HH + h]);
    float cn = fg * c[idx] + ig * gg;
    c[idx] = cn;
    float hn = og * tanhf(cn);
    hA[(size_t)b * ldA + h] = hn;
    hB[(size_t)b * ldB + h] = hn;
}

// ---------------- host ----------------
extern "C" void kernel_launch(void* const* d_in, const int* in_sizes, int n_in,
                              void* d_out, int out_size) {
    const float* encoder_out = (const float*)d_in[0];
    const float* h0   = (const float*)d_in[1];
    const float* c0   = (const float*)d_in[2];
    const int*   targets = (const int*)d_in[3];
    const int*   mask    = (const int*)d_in[4];
    const float* emb   = (const float*)d_in[5];
    const float* W_enc = (const float*)d_in[6];
    const float* W_dec = (const float*)d_in[7];
    const float* vvec  = (const float*)d_in[8];
    const float* W_ih0 = (const float*)d_in[9];
    const float* W_hh0 = (const float*)d_in[10];
    const float* b_ih0 = (const float*)d_in[11];
    const float* b_hh0 = (const float*)d_in[12];
    const float* W_ih1 = (const float*)d_in[13];
    const float* W_hh1 = (const float*)d_in[14];
    const float* b_ih1 = (const float*)d_in[15];
    const float* b_hh1 = (const float*)d_in[16];
    const float* W_out = (const float*)d_in[17];
    const float* b_out = (const float*)d_in[18];
    float* out = (float*)d_out;  // (B,T,V)

    float *p_enc_proj, *p_xemb, *p_gates_emb, *p_Wc0, *p_Wc1;
    float *p_xbuf, *p_x1buf, *p_x2buf, *p_gates, *p_c0, *p_c1, *p_decproj;
    cudaGetSymbolAddress((void**)&p_enc_proj, g_enc_proj);
    cudaGetSymbolAddress((void**)&p_xemb, g_xemb);
    cudaGetSymbolAddress((void**)&p_gates_emb, g_gates_emb);
    cudaGetSymbolAddress((void**)&p_Wc0, g_Wc0);
    cudaGetSymbolAddress((void**)&p_Wc1, g_Wc1);
    cudaGetSymbolAddress((void**)&p_xbuf, g_xbuf);
    cudaGetSymbolAddress((void**)&p_x1buf, g_x1buf);
    cudaGetSymbolAddress((void**)&p_x2buf, g_x2buf);
    cudaGetSymbolAddress((void**)&p_gates, g_gates);
    cudaGetSymbolAddress((void**)&p_c0, g_c0buf);
    cudaGetSymbolAddress((void**)&p_c1, g_c1buf);
    cudaGetSymbolAddress((void**)&p_decproj, g_decproj);

    // ---- precompute (parallel over all timesteps) ----
    embed_kernel<<<(BB * TT * EE) / 256, 256>>>(targets, emb, p_xemb);
    {
        int total = G4H * (DENC + HH) + G4H * (HH + HH);
        build_wcomb_kernel<<<(total + 255) / 256, 256>>>(W_ih0, W_hh0, W_ih1, W_hh1, p_Wc0, p_Wc1);
    }
    init_state_kernel<<<(BB * HH) / 256, 256>>>(h0, c0, p_xbuf, p_x1buf, p_c0, p_c1);

    // enc_proj (B*S, H) = encoder_out (B*S, DENC) @ W_enc^T
    gemm<128, 128, 16, 8, 8>(BB * SS, HH, DENC, encoder_out, DENC, W_enc, DENC, p_enc_proj, HH);
    // gates_emb (B*T, 4H) = x_emb @ W_ih0[:, :E]^T
    gemm<128, 128, 16, 8, 8>(BB * TT, G4H, EE, p_xemb, EE, W_ih0, EE + DENC, p_gates_emb, G4H);
    // pred_emb -> out directly: (B*T, V) = x_emb @ W_out[:, H+DENC:]^T + b_out
    gemm<64, 64, 16, 4, 4>(BB * TT, VV, EE, p_xemb, EE, W_out + (HH + DENC), HH + DENC + EE,
                           out, VV, nullptr, 0, b_out, nullptr, false);

    // ---- sequential decode ----
    for (int t = 0; t < TT; t++) {
        // dec_proj = h1 @ W_dec^T   (h1 lives in x1buf cols [H, 2H))
        gemm<64, 64, 16, 4, 4>(BB, HH, HH, p_x1buf + HH, HH + HH, W_dec, HH, p_decproj, HH);

        attention_kernel<<<BB, 256>>>(p_enc_proj, encoder_out, p_decproj, vvec, mask,
                                      p_xbuf, p_x2buf);

        // gates0 = [context|h0] @ [W_ih0[:,E:]|W_hh0]^T + gates_emb[:,t,:] + b_ih0 + b_hh0
        gemm<64, 128, 16, 4, 8>(BB, G4H, DENC + HH, p_xbuf, DENC + HH, p_Wc0, DENC + HH,
                                p_gates, G4H, p_gates_emb + (size_t)t * G4H, TT * G4H,
                                b_ih0, b_hh0, false);
        lstm_cell_kernel<<<(BB * HH) / 256, 256>>>(p_gates, p_c0,
                                                   p_x1buf, HH + HH,          // h0n -> x1buf[:, :H]
                                                   p_xbuf + DENC, DENC + HH); // h0n -> xbuf[:, DENC:]

        // gates1 = [h0n|h1] @ [W_ih1|W_hh1]^T + b_ih1 + b_hh1
        gemm<64, 128, 16, 4, 8>(BB, G4H, HH + HH, p_x1buf, HH + HH, p_Wc1, HH + HH,
                                p_gates, G4H, nullptr, 0, b_ih1, b_hh1, false);
        lstm_cell_kernel<<<(BB * HH) / 256, 256>>>(p_gates, p_c1,
                                                   p_x1buf + HH, HH + HH,     // h1n -> x1buf[:, H:]
                                                   p_x2buf, HH + DENC);       // h1n -> x2buf[:, :H]

        // pred[:, t, :] += [h1n|context] @ W_out[:, :H+DENC]^T   (pred_emb+b_out already there)
        gemm<64, 64, 16, 4, 4>(BB, VV, HH + DENC, p_x2buf, HH + DENC, W_out, HH + DENC + EE,
                               out + (size_t)t * VV, TT * VV, nullptr, 0, nullptr, nullptr, true);
    }
}

// round 2
// speedup vs baseline: 2.0790x; 2.0790x over previous
#include <cuda_runtime.h>
#include <math.h>
#include <stdint.h>

#define BB 512
#define SS 64
#define TT 32
#define VV 128
#define EE 256
#define HH 512
#define DENC 1024
#define G4H 2048
#define EOS_IDX 2
#define PCOL (HH + DENC)  /* 1536 */

// ---------------- scratch (device globals; no allocations) ----------------
__device__ float g_enc_proj[(size_t)BB * SS * HH];     // 64 MB
__device__ float g_xemb[(size_t)BB * TT * EE];         // 16 MB
__device__ float g_gates_emb[(size_t)BB * TT * G4H];   // 128 MB
__device__ float g_pred[(size_t)BB * TT * PCOL];       // 100 MB  [h1n | context] per (b,t)
__device__ float g_Wc0[G4H * (DENC + HH)];             // [W_ih0[:,E:] | W_hh0]
__device__ float g_Wc1[G4H * (HH + HH)];               // [W_ih1 | W_hh1]
__device__ float g_xbuf[BB * (DENC + HH)];             // [context | h0]
__device__ float g_x1buf[BB * (HH + HH)];              // [h0n | h1]
__device__ float g_gates[BB * G4H];
__device__ float g_c0buf[BB * HH];
__device__ float g_c1buf[BB * HH];
__device__ float g_decproj[BB * HH];

__device__ __forceinline__ float sigmoidf_(float x) { return 1.0f / (1.0f + expf(-x)); }

__device__ __forceinline__ uint32_t f2tf32(float x) {
    uint32_t r;
    asm("cvt.rna.tf32.f32 %0, %1;" : "=r"(r) : "f"(x));
    return r;
}

__device__ __forceinline__ void mma_tf32(float* c, const uint32_t* a, const uint32_t* b) {
    asm volatile(
        "mma.sync.aligned.m16n8k8.row.col.f32.tf32.tf32.f32 "
        "{%0,%1,%2,%3},{%4,%5,%6,%7},{%8,%9},{%0,%1,%2,%3};"
        : "+f"(c[0]), "+f"(c[1]), "+f"(c[2]), "+f"(c[3])
        : "r"(a[0]), "r"(a[1]), "r"(a[2]), "r"(a[3]), "r"(b[0]), "r"(b[1]));
}

// ---------------- TF32 tensor-core NT GEMM: C[M,N] = A(MxK) * B(NxK)^T ----------------
// Optional: + bias0[n] + bias1[n] + Cin[m,n]; optional accumulate into C.
template <int BM, int BN, int BK, int WM, int WN>
__global__ void __launch_bounds__((BM / WM) * (BN / WN) * 32)
mma_nt_kernel(int M, int N, int K,
              const float* __restrict__ A, int lda,
              const float* __restrict__ B, int ldb,
              float* __restrict__ C, int ldc,
              const float* __restrict__ Cin, int ldcin,
              const float* __restrict__ bias0,
              const float* __restrict__ bias1,
              int accumulate) {
    constexpr int WARPS_M = BM / WM, WARPS_N = BN / WN;
    constexpr int NW = WARPS_M * WARPS_N, THREADS = NW * 32;
    constexpr int MI = WM / 16, NI = WN / 8, KI = BK / 8;
    constexpr int PAD = 8;
    __shared__ uint32_t As[BK][BM + PAD];
    __shared__ uint32_t Bs[BK][BN + PAD];

    const int tid = threadIdx.x;
    const int wid = tid >> 5, lane = tid & 31;
    const int wm = (wid / WARPS_N) * WM, wn = (wid % WARPS_N) * WN;
    const int g = lane >> 2, tg = lane & 3;
    const int bm = blockIdx.y * BM, bn = blockIdx.x * BN;

    float acc[MI][NI][4];
#pragma unroll
    for (int i = 0; i < MI; i++)
#pragma unroll
        for (int j = 0; j < NI; j++)
#pragma unroll
            for (int q = 0; q < 4; q++) acc[i][j][q] = 0.0f;

    constexpr int A_LD4 = BM * (BK / 4) / THREADS;
    constexpr int B_LD4 = BN * (BK / 4) / THREADS;

    for (int k0 = 0; k0 < K; k0 += BK) {
#pragma unroll
        for (int i = 0; i < A_LD4; i++) {
            int idx = tid + i * THREADS;
            int m = idx / (BK / 4), kq = (idx % (BK / 4)) * 4;
            float4 v = *(const float4*)(A + (size_t)(bm + m) * lda + k0 + kq);
            As[kq + 0][m] = f2tf32(v.x);
            As[kq + 1][m] = f2tf32(v.y);
            As[kq + 2][m] = f2tf32(v.z);
            As[kq + 3][m] = f2tf32(v.w);
        }
#pragma unroll
        for (int i = 0; i < B_LD4; i++) {
            int idx = tid + i * THREADS;
            int n = idx / (BK / 4), kq = (idx % (BK / 4)) * 4;
            float4 v = *(const float4*)(B + (size_t)(bn + n) * ldb + k0 + kq);
            Bs[kq + 0][n] = f2tf32(v.x);
            Bs[kq + 1][n] = f2tf32(v.y);
            Bs[kq + 2][n] = f2tf32(v.z);
            Bs[kq + 3][n] = f2tf32(v.w);
        }
        __syncthreads();
#pragma unroll
        for (int ki = 0; ki < KI; ki++) {
            uint32_t af[MI][4];
            uint32_t bf[NI][2];
#pragma unroll
            for (int mi = 0; mi < MI; mi++) {
                int mrow = wm + mi * 16 + g;
                af[mi][0] = As[ki * 8 + tg][mrow];
                af[mi][1] = As[ki * 8 + tg][mrow + 8];
                af[mi][2] = As[ki * 8 + tg + 4][mrow];
                af[mi][3] = As[ki * 8 + tg + 4][mrow + 8];
            }
#pragma unroll
            for (int ni = 0; ni < NI; ni++) {
                int ncol = wn + ni * 8 + g;
                bf[ni][0] = Bs[ki * 8 + tg][ncol];
                bf[ni][1] = Bs[ki * 8 + tg + 4][ncol];
            }
#pragma unroll
            for (int mi = 0; mi < MI; mi++)
#pragma unroll
                for (int ni = 0; ni < NI; ni++) mma_tf32(acc[mi][ni], af[mi], bf[ni]);
        }
        __syncthreads();
    }

    // epilogue
#pragma unroll
    for (int mi = 0; mi < MI; mi++) {
#pragma unroll
        for (int ni = 0; ni < NI; ni++) {
            const int col = bn + wn + ni * 8 + tg * 2;
#pragma unroll
            for (int half = 0; half < 2; half++) {
                const int row = bm + wm + mi * 16 + g + half * 8;
                float v0 = acc[mi][ni][half * 2 + 0];
                float v1 = acc[mi][ni][half * 2 + 1];
                if (bias0) { v0 += bias0[col]; v1 += bias0[col + 1]; }
                if (bias1) { v0 += bias1[col]; v1 += bias1[col + 1]; }
                if (Cin) {
                    float2 ci = *(const float2*)(Cin + (size_t)row * ldcin + col);
                    v0 += ci.x; v1 += ci.y;
                }
                float2* cp = (float2*)(C + (size_t)row * ldc + col);
                if (accumulate) {
                    float2 c = *cp;
                    v0 += c.x; v1 += c.y;
                }
                *cp = make_float2(v0, v1);
            }
        }
    }
}

template <int BM, int BN, int BK, int WM, int WN>
static void mgemm(int M, int N, int K,
                  const float* A, int lda, const float* B, int ldb,
                  float* C, int ldc,
                  const float* Cin = nullptr, int ldcin = 0,
                  const float* bias0 = nullptr, const float* bias1 = nullptr,
                  bool accumulate = false) {
    dim3 grid(N / BN, M / BM);
    mma_nt_kernel<BM, BN, BK, WM, WN><<<grid, (BM / WM) * (BN / WN) * 32>>>(
        M, N, K, A, lda, B, ldb, C, ldc, Cin, ldcin, bias0, bias1, accumulate ? 1 : 0);
}

// ---------------- precompute kernels ----------------
__global__ void embed_kernel(const int* __restrict__ targets,
                             const float* __restrict__ emb,
                             float* __restrict__ xemb) {
    int idx = blockIdx.x * blockDim.x + threadIdx.x;  // B*T*E
    int e = idx & (EE - 1);
    int m = idx >> 8;        // b*T + t
    int t = m & (TT - 1);
    int b = m >> 5;
    int tok = (t == 0) ? EOS_IDX : targets[b * TT + t - 1];
    xemb[idx] = emb[(size_t)tok * EE + e];
}

__global__ void build_wcomb_kernel(const float* __restrict__ W_ih0,
                                   const float* __restrict__ W_hh0,
                                   const float* __restrict__ W_ih1,
                                   const float* __restrict__ W_hh1,
                                   float* __restrict__ Wc0,
                                   float* __restrict__ Wc1) {
    int idx = blockIdx.x * blockDim.x + threadIdx.x;
    const int N0 = G4H * (DENC + HH);
    const int N1 = G4H * (HH + HH);
    if (idx < N0) {
        int n = idx / (DENC + HH);
        int k = idx % (DENC + HH);
        Wc0[idx] = (k < DENC) ? W_ih0[(size_t)n * (EE + DENC) + EE + k]
                              : W_hh0[(size_t)n * HH + (k - DENC)];
    } else if (idx < N0 + N1) {
        int r = idx - N0;
        int n = r / (HH + HH);
        int k = r % (HH + HH);
        Wc1[r] = (k < HH) ? W_ih1[(size_t)n * HH + k]
                          : W_hh1[(size_t)n * HH + (k - HH)];
    }
}

__global__ void init_state_kernel(const float* __restrict__ h0,
                                  const float* __restrict__ c0,
                                  float* __restrict__ xbuf,
                                  float* __restrict__ x1buf,
                                  float* __restrict__ cb0,
                                  float* __restrict__ cb1) {
    int idx = blockIdx.x * blockDim.x + threadIdx.x;  // B*H
    int b = idx >> 9;
    int h = idx & (HH - 1);
    xbuf[(size_t)b * (DENC + HH) + DENC + h] = h0[idx];                 // layer 0 h
    x1buf[(size_t)b * (HH + HH) + HH + h] = h0[(size_t)BB * HH + idx];  // layer 1 h
    cb0[idx] = c0[idx];
    cb1[idx] = c0[(size_t)BB * HH + idx];
}

// ---------------- attention (fused score/tanh + masked softmax + context) ----------------
__global__ void __launch_bounds__(256) attention_kernel(
    const float* __restrict__ enc_proj,   // (B,S,H)
    const float* __restrict__ enc,        // (B,S,DENC)
    const float* __restrict__ decp,       // (B,H)
    const float* __restrict__ vvec,       // (H)
    const int* __restrict__ mask,         // (B,S)
    float* __restrict__ ctx_dst1, int ld1,  // xbuf: col 0
    float* __restrict__ ctx_dst2, int ld2)  // pred slice: col 0 (already offset by H)
{
    const int b = blockIdx.x;
    __shared__ float s_dp[HH];
    __shared__ float s_v[HH];
    __shared__ float s_w[SS];
    __shared__ float s_red[2];
    const int tid = threadIdx.x;
    const int warp = tid >> 5, lane = tid & 31;

    for (int i = tid; i < HH; i += 256) {
        s_dp[i] = decp[(size_t)b * HH + i];
        s_v[i] = vvec[i];
    }
    __syncthreads();

    for (int s = warp; s < SS; s += 8) {
        const float* ep = enc_proj + ((size_t)b * SS + s) * HH;
        float acc = 0.0f;
        for (int h = lane; h < HH; h += 32)
            acc += s_v[h] * tanhf(s_dp[h] + ep[h]);
#pragma unroll
        for (int o = 16; o; o >>= 1) acc += __shfl_xor_sync(0xffffffffu, acc, o);
        if (lane == 0) s_w[s] = mask[b * SS + s] ? acc : -1e30f;
    }
    __syncthreads();

    if (warp == 0) {
        float m = fmaxf(s_w[lane], s_w[lane + 32]);
#pragma unroll
        for (int o = 16; o; o >>= 1) m = fmaxf(m, __shfl_xor_sync(0xffffffffu, m, o));
        float sum = expf(s_w[lane] - m) + expf(s_w[lane + 32] - m);
#pragma unroll
        for (int o = 16; o; o >>= 1) sum += __shfl_xor_sync(0xffffffffu, sum, o);
        if (lane == 0) { s_red[0] = m; s_red[1] = sum; }
    }
    __syncthreads();
    const float m = s_red[0], inv = 1.0f / s_red[1];
    if (tid < SS) s_w[tid] = expf(s_w[tid] - m) * inv;
    __syncthreads();

    const float* eb = enc + (size_t)b * SS * DENC;
    for (int d = tid; d < DENC; d += 256) {
        float acc = 0.0f;
#pragma unroll 8
        for (int s = 0; s < SS; s++) acc += s_w[s] * eb[(size_t)s * DENC + d];
        ctx_dst1[(size_t)b * ld1 + d] = acc;
        ctx_dst2[(size_t)b * ld2 + d] = acc;
    }
}

// ---------------- LSTM pointwise cell ----------------
__global__ void lstm_cell_kernel(const float* __restrict__ gates,  // (B,4H)
                                 float* __restrict__ c,            // (B,H) in/out
                                 float* __restrict__ hA, int ldA,
                                 float* __restrict__ hB, int ldB) {
    int idx = blockIdx.x * blockDim.x + threadIdx.x;  // B*H
    int b = idx >> 9;
    int h = idx & (HH - 1);
    const float* g = gates + (size_t)b * G4H;
    float ig = sigmoidf_(g[h]);
    float fg = sigmoidf_(g[HH + h]);
    float gg = tanhf(g[2 * HH + h]);
    float og = sigmoidf_(g[3 * HH + h]);
    float cn = fg * c[idx] + ig * gg;
    c[idx] = cn;
    float hn = og * tanhf(cn);
    hA[(size_t)b * ldA + h] = hn;
    hB[(size_t)b * ldB + h] = hn;
}

// ---------------- host ----------------
extern "C" void kernel_launch(void* const* d_in, const int* in_sizes, int n_in,
                              void* d_out, int out_size) {
    const float* encoder_out = (const float*)d_in[0];
    const float* h0   = (const float*)d_in[1];
    const float* c0   = (const float*)d_in[2];
    const int*   targets = (const int*)d_in[3];
    const int*   mask    = (const int*)d_in[4];
    const float* emb   = (const float*)d_in[5];
    const float* W_enc = (const float*)d_in[6];
    const float* W_dec = (const float*)d_in[7];
    const float* vvec  = (const float*)d_in[8];
    const float* W_ih0 = (const float*)d_in[9];
    const float* W_hh0 = (const float*)d_in[10];
    const float* b_ih0 = (const float*)d_in[11];
    const float* b_hh0 = (const float*)d_in[12];
    const float* W_ih1 = (const float*)d_in[13];
    const float* W_hh1 = (const float*)d_in[14];
    const float* b_ih1 = (const float*)d_in[15];
    const float* b_hh1 = (const float*)d_in[16];
    const float* W_out = (const float*)d_in[17];
    const float* b_out = (const float*)d_in[18];
    float* out = (float*)d_out;  // (B,T,V)

    float *p_enc_proj, *p_xemb, *p_gates_emb, *p_pred, *p_Wc0, *p_Wc1;
    float *p_xbuf, *p_x1buf, *p_gates, *p_c0, *p_c1, *p_decproj;
    cudaGetSymbolAddress((void**)&p_enc_proj, g_enc_proj);
    cudaGetSymbolAddress((void**)&p_xemb, g_xemb);
    cudaGetSymbolAddress((void**)&p_gates_emb, g_gates_emb);
    cudaGetSymbolAddress((void**)&p_pred, g_pred);
    cudaGetSymbolAddress((void**)&p_Wc0, g_Wc0);
    cudaGetSymbolAddress((void**)&p_Wc1, g_Wc1);
    cudaGetSymbolAddress((void**)&p_xbuf, g_xbuf);
    cudaGetSymbolAddress((void**)&p_x1buf, g_x1buf);
    cudaGetSymbolAddress((void**)&p_gates, g_gates);
    cudaGetSymbolAddress((void**)&p_c0, g_c0buf);
    cudaGetSymbolAddress((void**)&p_c1, g_c1buf);
    cudaGetSymbolAddress((void**)&p_decproj, g_decproj);

    // ---- precompute (parallel over all timesteps) ----
    embed_kernel<<<(BB * TT * EE) / 256, 256>>>(targets, emb, p_xemb);
    {
        int total = G4H * (DENC + HH) + G4H * (HH + HH);
        build_wcomb_kernel<<<(total + 255) / 256, 256>>>(W_ih0, W_hh0, W_ih1, W_hh1, p_Wc0, p_Wc1);
    }
    init_state_kernel<<<(BB * HH) / 256, 256>>>(h0, c0, p_xbuf, p_x1buf, p_c0, p_c1);

    // enc_proj (B*S, H) = encoder_out (B*S, DENC) @ W_enc^T
    mgemm<128, 128, 16, 64, 32>(BB * SS, HH, DENC, encoder_out, DENC, W_enc, DENC,
                                p_enc_proj, HH);
    // gates_emb (B*T, 4H) = x_emb @ W_ih0[:, :E]^T
    mgemm<128, 128, 16, 64, 32>(BB * TT, G4H, EE, p_xemb, EE, W_ih0, EE + DENC,
                                p_gates_emb, G4H);
    // pred_emb -> out directly: (B*T, V) = x_emb @ W_out[:, H+DENC:]^T + b_out
    mgemm<128, 128, 16, 64, 32>(BB * TT, VV, EE, p_xemb, EE, W_out + (HH + DENC),
                                HH + DENC + EE, out, VV, nullptr, 0, b_out, nullptr, false);

    // ---- sequential decode ----
    for (int t = 0; t < TT; t++) {
        // dec_proj = h1 @ W_dec^T   (h1 lives in x1buf cols [H, 2H))
        mgemm<64, 128, 16, 32, 64>(BB, HH, HH, p_x1buf + HH, HH + HH, W_dec, HH,
                                   p_decproj, HH);

        // attention: context -> xbuf[:, :DENC] and pred[:, t, H:]
        attention_kernel<<<BB, 256>>>(p_enc_proj, encoder_out, p_decproj, vvec, mask,
                                      p_xbuf, DENC + HH,
                                      p_pred + (size_t)t * PCOL + HH, TT * PCOL);

        // gates0 = [context|h0] @ Wc0^T + gates_emb[:,t,:] + b_ih0 + b_hh0
        mgemm<64, 128, 16, 32, 64>(BB, G4H, DENC + HH, p_xbuf, DENC + HH, p_Wc0, DENC + HH,
                                   p_gates, G4H, p_gates_emb + (size_t)t * G4H, TT * G4H,
                                   b_ih0, b_hh0, false);
        lstm_cell_kernel<<<(BB * HH) / 256, 256>>>(p_gates, p_c0,
                                                   p_x1buf, HH + HH,           // h0n -> x1buf[:, :H]
                                                   p_xbuf + DENC, DENC + HH);  // h0n -> xbuf[:, DENC:]

        // gates1 = [h0n|h1] @ Wc1^T + b_ih1 + b_hh1
        mgemm<64, 128, 16, 32, 64>(BB, G4H, HH + HH, p_x1buf, HH + HH, p_Wc1, HH + HH,
                                   p_gates, G4H, nullptr, 0, b_ih1, b_hh1, false);
        lstm_cell_kernel<<<(BB * HH) / 256, 256>>>(p_gates, p_c1,
                                                   p_x1buf + HH, HH + HH,       // h1n -> x1buf[:, H:]
                                                   p_pred + (size_t)t * PCOL, TT * PCOL); // h1n -> pred[:, t, :H]

        // NOTE: per-step pred GEMM removed — deferred to one big GEMM below.
    }

    // pred logits: out += [h1n|context]_(B*T,1536) @ W_out[:, :H+DENC]^T
    mgemm<128, 128, 16, 64, 32>(BB * TT, VV, PCOL, p_pred, PCOL, W_out, HH + DENC + EE,
                                out, VV, nullptr, 0, nullptr, nullptr, true);
}

// round 3
// speedup vs baseline: 2.3083x; 1.1103x over previous
#include <cuda_runtime.h>
#include <math.h>
#include <stdint.h>

#define BB 512
#define SS 64
#define TT 32
#define VV 128
#define EE 256
#define HH 512
#define DENC 1024
#define G4H 2048
#define EOS_IDX 2
#define PCOL (HH + DENC)  /* 1536 */

// ---------------- scratch (device globals; no allocations) ----------------
__device__ float g_enc_proj[(size_t)BB * SS * HH];     // 64 MB
__device__ float g_xemb[(size_t)BB * TT * EE];         // 16 MB
__device__ float g_gates_emb[(size_t)BB * TT * G4H];   // 128 MB
__device__ float g_pred[(size_t)BB * TT * PCOL];       // 100 MB  [h1n | context] per (b,t)
__device__ float g_Wc0[G4H * (DENC + HH)];             // [W_ih0[:,E:] | W_hh0]
__device__ float g_Wc1[G4H * (HH + HH)];               // [W_ih1 | W_hh1]
__device__ float g_xbuf[BB * (DENC + HH)];             // [context | h0]
__device__ float g_x1buf[BB * (HH + HH)];              // [h0n | h1]
__device__ float g_gates[BB * G4H];
__device__ float g_c0buf[BB * HH];
__device__ float g_c1buf[BB * HH];
__device__ float g_decproj[BB * HH];

__device__ __forceinline__ float sigmoidf_(float x) { return 1.0f / (1.0f + expf(-x)); }

__device__ __forceinline__ uint32_t f2tf32(float x) {
    uint32_t r;
    asm("cvt.rna.tf32.f32 %0, %1;" : "=r"(r) : "f"(x));
    return r;
}

__device__ __forceinline__ void mma_tf32(float* c, const uint32_t* a, const uint32_t* b) {
    asm volatile(
        "mma.sync.aligned.m16n8k8.row.col.f32.tf32.tf32.f32 "
        "{%0,%1,%2,%3},{%4,%5,%6,%7},{%8,%9},{%0,%1,%2,%3};"
        : "+f"(c[0]), "+f"(c[1]), "+f"(c[2]), "+f"(c[3])
        : "r"(a[0]), "r"(a[1]), "r"(a[2]), "r"(a[3]), "r"(b[0]), "r"(b[1]));
}

// ---------------- TF32 tensor-core NT GEMM, 2-stage double buffered ----------------
// C[M,N] = A(MxK) * B(NxK)^T  (+bias0[n] +bias1[n] +Cin[m,n]; optional += C)
template <int BM, int BN, int BK, int WM, int WN>
__global__ void __launch_bounds__((BM / WM) * (BN / WN) * 32)
mma_nt_kernel(int M, int N, int K,
              const float* __restrict__ A, int lda,
              const float* __restrict__ B, int ldb,
              float* __restrict__ C, int ldc,
              const float* __restrict__ Cin, int ldcin,
              const float* __restrict__ bias0,
              const float* __restrict__ bias1,
              int accumulate) {
    constexpr int WARPS_M = BM / WM, WARPS_N = BN / WN;
    constexpr int NW = WARPS_M * WARPS_N, THREADS = NW * 32;
    constexpr int MI = WM / 16, NI = WN / 8, KI = BK / 8;
    constexpr int PAD = 8;
    constexpr int A_LD4 = BM * (BK / 4) / THREADS;  // float4 loads per thread (A)
    constexpr int B_LD4 = BN * (BK / 4) / THREADS;  // float4 loads per thread (B)

    __shared__ uint32_t As[2][BK][BM + PAD];
    __shared__ uint32_t Bs[2][BK][BN + PAD];

    const int tid = threadIdx.x;
    const int wid = tid >> 5, lane = tid & 31;
    const int wm = (wid / WARPS_N) * WM, wn = (wid % WARPS_N) * WN;
    const int g = lane >> 2, tg = lane & 3;
    const int bm = blockIdx.y * BM, bn = blockIdx.x * BN;

    float acc[MI][NI][4];
#pragma unroll
    for (int i = 0; i < MI; i++)
#pragma unroll
        for (int j = 0; j < NI; j++)
#pragma unroll
            for (int q = 0; q < 4; q++) acc[i][j][q] = 0.0f;

    float4 ra[A_LD4], rb[B_LD4];

    // ---- load tile k0 into registers ----
    auto load_tile = [&](int k0) {
#pragma unroll
        for (int i = 0; i < A_LD4; i++) {
            int idx = tid + i * THREADS;
            int m = idx / (BK / 4), kq = (idx % (BK / 4)) * 4;
            ra[i] = *(const float4*)(A + (size_t)(bm + m) * lda + k0 + kq);
        }
#pragma unroll
        for (int i = 0; i < B_LD4; i++) {
            int idx = tid + i * THREADS;
            int n = idx / (BK / 4), kq = (idx % (BK / 4)) * 4;
            rb[i] = *(const float4*)(B + (size_t)(bn + n) * ldb + k0 + kq);
        }
    };
    // ---- convert + store registers into smem stage `buf` ----
    auto store_tile = [&](int buf) {
#pragma unroll
        for (int i = 0; i < A_LD4; i++) {
            int idx = tid + i * THREADS;
            int m = idx / (BK / 4), kq = (idx % (BK / 4)) * 4;
            As[buf][kq + 0][m] = f2tf32(ra[i].x);
            As[buf][kq + 1][m] = f2tf32(ra[i].y);
            As[buf][kq + 2][m] = f2tf32(ra[i].z);
            As[buf][kq + 3][m] = f2tf32(ra[i].w);
        }
#pragma unroll
        for (int i = 0; i < B_LD4; i++) {
            int idx = tid + i * THREADS;
            int n = idx / (BK / 4), kq = (idx % (BK / 4)) * 4;
            Bs[buf][kq + 0][n] = f2tf32(rb[i].x);
            Bs[buf][kq + 1][n] = f2tf32(rb[i].y);
            Bs[buf][kq + 2][n] = f2tf32(rb[i].z);
            Bs[buf][kq + 3][n] = f2tf32(rb[i].w);
        }
    };

    load_tile(0);
    store_tile(0);
    __syncthreads();

    int buf = 0;
    for (int k0 = 0; k0 < K; k0 += BK) {
        const bool has_next = (k0 + BK) < K;
        if (has_next) load_tile(k0 + BK);  // LDG in flight during compute

#pragma unroll
        for (int ki = 0; ki < KI; ki++) {
            uint32_t af[MI][4];
            uint32_t bf[NI][2];
#pragma unroll
            for (int mi = 0; mi < MI; mi++) {
                int mrow = wm + mi * 16 + g;
                af[mi][0] = As[buf][ki * 8 + tg][mrow];
                af[mi][1] = As[buf][ki * 8 + tg][mrow + 8];
                af[mi][2] = As[buf][ki * 8 + tg + 4][mrow];
                af[mi][3] = As[buf][ki * 8 + tg + 4][mrow + 8];
            }
#pragma unroll
            for (int ni = 0; ni < NI; ni++) {
                int ncol = wn + ni * 8 + g;
                bf[ni][0] = Bs[buf][ki * 8 + tg][ncol];
                bf[ni][1] = Bs[buf][ki * 8 + tg + 4][ncol];
            }
#pragma unroll
            for (int mi = 0; mi < MI; mi++)
#pragma unroll
                for (int ni = 0; ni < NI; ni++) mma_tf32(acc[mi][ni], af[mi], bf[ni]);
        }

        if (has_next) store_tile(buf ^ 1);
        __syncthreads();
        buf ^= 1;
    }

    // epilogue
#pragma unroll
    for (int mi = 0; mi < MI; mi++) {
#pragma unroll
        for (int ni = 0; ni < NI; ni++) {
            const int col = bn + wn + ni * 8 + tg * 2;
#pragma unroll
            for (int half = 0; half < 2; half++) {
                const int row = bm + wm + mi * 16 + g + half * 8;
                float v0 = acc[mi][ni][half * 2 + 0];
                float v1 = acc[mi][ni][half * 2 + 1];
                if (bias0) { v0 += bias0[col]; v1 += bias0[col + 1]; }
                if (bias1) { v0 += bias1[col]; v1 += bias1[col + 1]; }
                if (Cin) {
                    float2 ci = *(const float2*)(Cin + (size_t)row * ldcin + col);
                    v0 += ci.x; v1 += ci.y;
                }
                float2* cp = (float2*)(C + (size_t)row * ldc + col);
                if (accumulate) {
                    float2 c = *cp;
                    v0 += c.x; v1 += c.y;
                }
                *cp = make_float2(v0, v1);
            }
        }
    }
}

template <int BM, int BN, int BK, int WM, int WN>
static void mgemm(int M, int N, int K,
                  const float* A, int lda, const float* B, int ldb,
                  float* C, int ldc,
                  const float* Cin = nullptr, int ldcin = 0,
                  const float* bias0 = nullptr, const float* bias1 = nullptr,
                  bool accumulate = false) {
    dim3 grid(N / BN, M / BM);
    mma_nt_kernel<BM, BN, BK, WM, WN><<<grid, (BM / WM) * (BN / WN) * 32>>>(
        M, N, K, A, lda, B, ldb, C, ldc, Cin, ldcin, bias0, bias1, accumulate ? 1 : 0);
}

// ---------------- precompute kernels ----------------
__global__ void embed_kernel(const int* __restrict__ targets,
                             const float* __restrict__ emb,
                             float* __restrict__ xemb) {
    int idx = blockIdx.x * blockDim.x + threadIdx.x;  // B*T*E
    int e = idx & (EE - 1);
    int m = idx >> 8;        // b*T + t
    int t = m & (TT - 1);
    int b = m >> 5;
    int tok = (t == 0) ? EOS_IDX : targets[b * TT + t - 1];
    xemb[idx] = emb[(size_t)tok * EE + e];
}

__global__ void build_wcomb_kernel(const float* __restrict__ W_ih0,
                                   const float* __restrict__ W_hh0,
                                   const float* __restrict__ W_ih1,
                                   const float* __restrict__ W_hh1,
                                   float* __restrict__ Wc0,
                                   float* __restrict__ Wc1) {
    int idx = blockIdx.x * blockDim.x + threadIdx.x;
    const int N0 = G4H * (DENC + HH);
    const int N1 = G4H * (HH + HH);
    if (idx < N0) {
        int n = idx / (DENC + HH);
        int k = idx % (DENC + HH);
        Wc0[idx] = (k < DENC) ? W_ih0[(size_t)n * (EE + DENC) + EE + k]
                              : W_hh0[(size_t)n * HH + (k - DENC)];
    } else if (idx < N0 + N1) {
        int r = idx - N0;
        int n = r / (HH + HH);
        int k = r % (HH + HH);
        Wc1[r] = (k < HH) ? W_ih1[(size_t)n * HH + k]
                          : W_hh1[(size_t)n * HH + (k - HH)];
    }
}

__global__ void init_state_kernel(const float* __restrict__ h0,
                                  const float* __restrict__ c0,
                                  float* __restrict__ xbuf,
                                  float* __restrict__ x1buf,
                                  float* __restrict__ cb0,
                                  float* __restrict__ cb1) {
    int idx = blockIdx.x * blockDim.x + threadIdx.x;  // B*H
    int b = idx >> 9;
    int h = idx & (HH - 1);
    xbuf[(size_t)b * (DENC + HH) + DENC + h] = h0[idx];                 // layer 0 h
    x1buf[(size_t)b * (HH + HH) + HH + h] = h0[(size_t)BB * HH + idx];  // layer 1 h
    cb0[idx] = c0[idx];
    cb1[idx] = c0[(size_t)BB * HH + idx];
}

// ---------------- attention (fused score/tanh + masked softmax + context) ----------------
__global__ void __launch_bounds__(256) attention_kernel(
    const float* __restrict__ enc_proj,   // (B,S,H)
    const float* __restrict__ enc,        // (B,S,DENC)
    const float* __restrict__ decp,       // (B,H)
    const float* __restrict__ vvec,       // (H)
    const int* __restrict__ mask,         // (B,S)
    float* __restrict__ ctx_dst1, int ld1,  // xbuf: col 0
    float* __restrict__ ctx_dst2, int ld2)  // pred slice (already offset by H)
{
    const int b = blockIdx.x;
    __shared__ float s_dp[HH];
    __shared__ float s_v[HH];
    __shared__ float s_w[SS];
    __shared__ float s_red[2];
    const int tid = threadIdx.x;
    const int warp = tid >> 5, lane = tid & 31;

    for (int i = tid; i < HH; i += 256) {
        s_dp[i] = decp[(size_t)b * HH + i];
        s_v[i] = vvec[i];
    }
    __syncthreads();

    for (int s = warp; s < SS; s += 8) {
        const float* ep = enc_proj + ((size_t)b * SS + s) * HH;
        float acc = 0.0f;
        for (int h = lane; h < HH; h += 32)
            acc += s_v[h] * tanhf(s_dp[h] + ep[h]);
#pragma unroll
        for (int o = 16; o; o >>= 1) acc += __shfl_xor_sync(0xffffffffu, acc, o);
        if (lane == 0) s_w[s] = mask[b * SS + s] ? acc : -1e30f;
    }
    __syncthreads();

    if (warp == 0) {
        float m = fmaxf(s_w[lane], s_w[lane + 32]);
#pragma unroll
        for (int o = 16; o; o >>= 1) m = fmaxf(m, __shfl_xor_sync(0xffffffffu, m, o));
        float sum = expf(s_w[lane] - m) + expf(s_w[lane + 32] - m);
#pragma unroll
        for (int o = 16; o; o >>= 1) sum += __shfl_xor_sync(0xffffffffu, sum, o);
        if (lane == 0) { s_red[0] = m; s_red[1] = sum; }
    }
    __syncthreads();
    const float m = s_red[0], inv = 1.0f / s_red[1];
    if (tid < SS) s_w[tid] = expf(s_w[tid] - m) * inv;
    __syncthreads();

    const float* eb = enc + (size_t)b * SS * DENC;
    for (int d = tid; d < DENC; d += 256) {
        float acc = 0.0f;
#pragma unroll 8
        for (int s = 0; s < SS; s++) acc += s_w[s] * eb[(size_t)s * DENC + d];
        ctx_dst1[(size_t)b * ld1 + d] = acc;
        ctx_dst2[(size_t)b * ld2 + d] = acc;
    }
}

// ---------------- LSTM pointwise cell ----------------
__global__ void lstm_cell_kernel(const float* __restrict__ gates,  // (B,4H)
                                 float* __restrict__ c,            // (B,H) in/out
                                 float* __restrict__ hA, int ldA,
                                 float* __restrict__ hB, int ldB) {
    int idx = blockIdx.x * blockDim.x + threadIdx.x;  // B*H
    int b = idx >> 9;
    int h = idx & (HH - 1);
    const float* g = gates + (size_t)b * G4H;
    float ig = sigmoidf_(g[h]);
    float fg = sigmoidf_(g[HH + h]);
    float gg = tanhf(g[2 * HH + h]);
    float og = sigmoidf_(g[3 * HH + h]);
    float cn = fg * c[idx] + ig * gg;
    c[idx] = cn;
    float hn = og * tanhf(cn);
    hA[(size_t)b * ldA + h] = hn;
    hB[(size_t)b * ldB + h] = hn;
}

// ---------------- host ----------------
extern "C" void kernel_launch(void* const* d_in, const int* in_sizes, int n_in,
                              void* d_out, int out_size) {
    const float* encoder_out = (const float*)d_in[0];
    const float* h0   = (const float*)d_in[1];
    const float* c0   = (const float*)d_in[2];
    const int*   targets = (const int*)d_in[3];
    const int*   mask    = (const int*)d_in[4];
    const float* emb   = (const float*)d_in[5];
    const float* W_enc = (const float*)d_in[6];
    const float* W_dec = (const float*)d_in[7];
    const float* vvec  = (const float*)d_in[8];
    const float* W_ih0 = (const float*)d_in[9];
    const float* W_hh0 = (const float*)d_in[10];
    const float* b_ih0 = (const float*)d_in[11];
    const float* b_hh0 = (const float*)d_in[12];
    const float* W_ih1 = (const float*)d_in[13];
    const float* W_hh1 = (const float*)d_in[14];
    const float* b_ih1 = (const float*)d_in[15];
    const float* b_hh1 = (const float*)d_in[16];
    const float* W_out = (const float*)d_in[17];
    const float* b_out = (const float*)d_in[18];
    float* out = (float*)d_out;  // (B,T,V)

    float *p_enc_proj, *p_xemb, *p_gates_emb, *p_pred, *p_Wc0, *p_Wc1;
    float *p_xbuf, *p_x1buf, *p_gates, *p_c0, *p_c1, *p_decproj;
    cudaGetSymbolAddress((void**)&p_enc_proj, g_enc_proj);
    cudaGetSymbolAddress((void**)&p_xemb, g_xemb);
    cudaGetSymbolAddress((void**)&p_gates_emb, g_gates_emb);
    cudaGetSymbolAddress((void**)&p_pred, g_pred);
    cudaGetSymbolAddress((void**)&p_Wc0, g_Wc0);
    cudaGetSymbolAddress((void**)&p_Wc1, g_Wc1);
    cudaGetSymbolAddress((void**)&p_xbuf, g_xbuf);
    cudaGetSymbolAddress((void**)&p_x1buf, g_x1buf);
    cudaGetSymbolAddress((void**)&p_gates, g_gates);
    cudaGetSymbolAddress((void**)&p_c0, g_c0buf);
    cudaGetSymbolAddress((void**)&p_c1, g_c1buf);
    cudaGetSymbolAddress((void**)&p_decproj, g_decproj);

    // ---- precompute (parallel over all timesteps) ----
    embed_kernel<<<(BB * TT * EE) / 256, 256>>>(targets, emb, p_xemb);
    {
        int total = G4H * (DENC + HH) + G4H * (HH + HH);
        build_wcomb_kernel<<<(total + 255) / 256, 256>>>(W_ih0, W_hh0, W_ih1, W_hh1, p_Wc0, p_Wc1);
    }
    init_state_kernel<<<(BB * HH) / 256, 256>>>(h0, c0, p_xbuf, p_x1buf, p_c0, p_c1);

    // enc_proj (B*S, H) = encoder_out (B*S, DENC) @ W_enc^T
    mgemm<128, 128, 16, 64, 32>(BB * SS, HH, DENC, encoder_out, DENC, W_enc, DENC,
                                p_enc_proj, HH);
    // gates_emb (B*T, 4H) = x_emb @ W_ih0[:, :E]^T
    mgemm<128, 128, 16, 64, 32>(BB * TT, G4H, EE, p_xemb, EE, W_ih0, EE + DENC,
                                p_gates_emb, G4H);
    // pred_emb -> out directly: (B*T, V) = x_emb @ W_out[:, H+DENC:]^T + b_out
    mgemm<128, 128, 16, 64, 32>(BB * TT, VV, EE, p_xemb, EE, W_out + (HH + DENC),
                                HH + DENC + EE, out, VV, nullptr, 0, b_out, nullptr, false);

    // ---- sequential decode ----
    for (int t = 0; t < TT; t++) {
        // dec_proj = h1 @ W_dec^T   (h1 lives in x1buf cols [H, 2H))
        mgemm<64, 64, 16, 32, 32>(BB, HH, HH, p_x1buf + HH, HH + HH, W_dec, HH,
                                  p_decproj, HH);

        // attention: context -> xbuf[:, :DENC] and pred[:, t, H:]
        attention_kernel<<<BB, 256>>>(p_enc_proj, encoder_out, p_decproj, vvec, mask,
                                      p_xbuf, DENC + HH,
                                      p_pred + (size_t)t * PCOL + HH, TT * PCOL);

        // gates0 = [context|h0] @ Wc0^T + gates_emb[:,t,:] + b_ih0 + b_hh0
        mgemm<64, 128, 16, 32, 64>(BB, G4H, DENC + HH, p_xbuf, DENC + HH, p_Wc0, DENC + HH,
                                   p_gates, G4H, p_gates_emb + (size_t)t * G4H, TT * G4H,
                                   b_ih0, b_hh0, false);
        lstm_cell_kernel<<<(BB * HH) / 256, 256>>>(p_gates, p_c0,
                                                   p_x1buf, HH + HH,           // h0n -> x1buf[:, :H]
                                                   p_xbuf + DENC, DENC + HH);  // h0n -> xbuf[:, DENC:]

        // gates1 = [h0n|h1] @ Wc1^T + b_ih1 + b_hh1
        mgemm<64, 128, 16, 32, 64>(BB, G4H, HH + HH, p_x1buf, HH + HH, p_Wc1, HH + HH,
                                   p_gates, G4H, nullptr, 0, b_ih1, b_hh1, false);
        lstm_cell_kernel<<<(BB * HH) / 256, 256>>>(p_gates, p_c1,
                                                   p_x1buf + HH, HH + HH,       // h1n -> x1buf[:, H:]
                                                   p_pred + (size_t)t * PCOL, TT * PCOL); // h1n -> pred[:, t, :H]
    }

    // pred logits: out += [h1n|context]_(B*T,1536) @ W_out[:, :H+DENC]^T
    mgemm<128, 128, 16, 64, 32>(BB * TT, VV, PCOL, p_pred, PCOL, W_out, HH + DENC + EE,
                                out, VV, nullptr, 0, nullptr, nullptr, true);
}

// round 4
// speedup vs baseline: 2.5987x; 1.1258x over previous
#include <cuda_runtime.h>
#include <cuda_bf16.h>
#include <math.h>
#include <stdint.h>

#define BB 512
#define SS 64
#define TT 32
#define VV 128
#define EE 256
#define HH 512
#define DENC 1024
#define G4H 2048
#define EOS_IDX 2
#define PCOL (HH + DENC)  /* 1536 */

// ---------------- scratch (device globals; no allocations) ----------------
__device__ __nv_bfloat16 g_encproj_bf[(size_t)BB * SS * HH];  // 32 MB (score path)
__device__ float g_xemb[(size_t)BB * TT * EE];         // 16 MB
__device__ float g_gates_emb[(size_t)BB * TT * G4H];   // 128 MB
__device__ float g_pred[(size_t)BB * TT * PCOL];       // 100 MB  [h1n | context] per (b,t)
__device__ float g_Wc0[G4H * (DENC + HH)];             // [W_ih0[:,E:] | W_hh0]
__device__ float g_Wc1[G4H * (HH + HH)];               // [W_ih1 | W_hh1]
__device__ float g_xbuf[BB * (DENC + HH)];             // [context | h0]
__device__ float g_x1buf[BB * (HH + HH)];              // [h0n | h1]
__device__ float g_gates[BB * G4H];
__device__ float g_c0buf[BB * HH];
__device__ float g_c1buf[BB * HH];
__device__ float g_decproj[BB * HH];

__device__ __forceinline__ float sigmoidf_(float x) { return 1.0f / (1.0f + expf(-x)); }

__device__ __forceinline__ uint32_t f2tf32(float x) {
    uint32_t r;
    asm("cvt.rna.tf32.f32 %0, %1;" : "=r"(r) : "f"(x));
    return r;
}

__device__ __forceinline__ void mma_tf32(float* c, const uint32_t* a, const uint32_t* b) {
    asm volatile(
        "mma.sync.aligned.m16n8k8.row.col.f32.tf32.tf32.f32 "
        "{%0,%1,%2,%3},{%4,%5,%6,%7},{%8,%9},{%0,%1,%2,%3};"
        : "+f"(c[0]), "+f"(c[1]), "+f"(c[2]), "+f"(c[3])
        : "r"(a[0]), "r"(a[1]), "r"(a[2]), "r"(a[3]), "r"(b[0]), "r"(b[1]));
}

// ---------------- TF32 tensor-core NT GEMM, 2-stage double buffered ----------------
// C[M,N] = A(MxK) * B(NxK)^T  (+bias0[n] +bias1[n] +Cin[m,n]; optional += C)
// out_bf16: write results as bf16 (no bias/Cin/accumulate in that mode).
template <int BM, int BN, int BK, int WM, int WN>
__global__ void __launch_bounds__((BM / WM) * (BN / WN) * 32, 2)
mma_nt_kernel(int M, int N, int K,
              const float* __restrict__ A, int lda,
              const float* __restrict__ B, int ldb,
              void* __restrict__ Cv, int ldc,
              const float* __restrict__ Cin, int ldcin,
              const float* __restrict__ bias0,
              const float* __restrict__ bias1,
              int accumulate, int out_bf16) {
    constexpr int WARPS_M = BM / WM, WARPS_N = BN / WN;
    constexpr int NW = WARPS_M * WARPS_N, THREADS = NW * 32;
    constexpr int MI = WM / 16, NI = WN / 8, KI = BK / 8;
    constexpr int PAD = 8;
    constexpr int A_LD4 = BM * (BK / 4) / THREADS;  // float4 loads per thread (A)
    constexpr int B_LD4 = BN * (BK / 4) / THREADS;  // float4 loads per thread (B)

    __shared__ uint32_t As[2][BK][BM + PAD];
    __shared__ uint32_t Bs[2][BK][BN + PAD];

    const int tid = threadIdx.x;
    const int wid = tid >> 5, lane = tid & 31;
    const int wm = (wid / WARPS_N) * WM, wn = (wid % WARPS_N) * WN;
    const int g = lane >> 2, tg = lane & 3;
    const int bm = blockIdx.y * BM, bn = blockIdx.x * BN;

    float acc[MI][NI][4];
#pragma unroll
    for (int i = 0; i < MI; i++)
#pragma unroll
        for (int j = 0; j < NI; j++)
#pragma unroll
            for (int q = 0; q < 4; q++) acc[i][j][q] = 0.0f;

    float4 ra[A_LD4], rb[B_LD4];

    auto load_tile = [&](int k0) {
#pragma unroll
        for (int i = 0; i < A_LD4; i++) {
            int idx = tid + i * THREADS;
            int m = idx / (BK / 4), kq = (idx % (BK / 4)) * 4;
            ra[i] = *(const float4*)(A + (size_t)(bm + m) * lda + k0 + kq);
        }
#pragma unroll
        for (int i = 0; i < B_LD4; i++) {
            int idx = tid + i * THREADS;
            int n = idx / (BK / 4), kq = (idx % (BK / 4)) * 4;
            rb[i] = *(const float4*)(B + (size_t)(bn + n) * ldb + k0 + kq);
        }
    };
    auto store_tile = [&](int buf) {
#pragma unroll
        for (int i = 0; i < A_LD4; i++) {
            int idx = tid + i * THREADS;
            int m = idx / (BK / 4), kq = (idx % (BK / 4)) * 4;
            As[buf][kq + 0][m] = f2tf32(ra[i].x);
            As[buf][kq + 1][m] = f2tf32(ra[i].y);
            As[buf][kq + 2][m] = f2tf32(ra[i].z);
            As[buf][kq + 3][m] = f2tf32(ra[i].w);
        }
#pragma unroll
        for (int i = 0; i < B_LD4; i++) {
            int idx = tid + i * THREADS;
            int n = idx / (BK / 4), kq = (idx % (BK / 4)) * 4;
            Bs[buf][kq + 0][n] = f2tf32(rb[i].x);
            Bs[buf][kq + 1][n] = f2tf32(rb[i].y);
            Bs[buf][kq + 2][n] = f2tf32(rb[i].z);
            Bs[buf][kq + 3][n] = f2tf32(rb[i].w);
        }
    };

    load_tile(0);
    store_tile(0);
    __syncthreads();

    int buf = 0;
    for (int k0 = 0; k0 < K; k0 += BK) {
        const bool has_next = (k0 + BK) < K;
        if (has_next) load_tile(k0 + BK);  // LDG in flight during compute

#pragma unroll
        for (int ki = 0; ki < KI; ki++) {
            uint32_t af[MI][4];
            uint32_t bf[NI][2];
#pragma unroll
            for (int mi = 0; mi < MI; mi++) {
                int mrow = wm + mi * 16 + g;
                af[mi][0] = As[buf][ki * 8 + tg][mrow];
                af[mi][1] = As[buf][ki * 8 + tg][mrow + 8];
                af[mi][2] = As[buf][ki * 8 + tg + 4][mrow];
                af[mi][3] = As[buf][ki * 8 + tg + 4][mrow + 8];
            }
#pragma unroll
            for (int ni = 0; ni < NI; ni++) {
                int ncol = wn + ni * 8 + g;
                bf[ni][0] = Bs[buf][ki * 8 + tg][ncol];
                bf[ni][1] = Bs[buf][ki * 8 + tg + 4][ncol];
            }
#pragma unroll
            for (int mi = 0; mi < MI; mi++)
#pragma unroll
                for (int ni = 0; ni < NI; ni++) mma_tf32(acc[mi][ni], af[mi], bf[ni]);
        }

        if (has_next) store_tile(buf ^ 1);
        __syncthreads();
        buf ^= 1;
    }

    // epilogue
#pragma unroll
    for (int mi = 0; mi < MI; mi++) {
#pragma unroll
        for (int ni = 0; ni < NI; ni++) {
            const int col = bn + wn + ni * 8 + tg * 2;
#pragma unroll
            for (int half = 0; half < 2; half++) {
                const int row = bm + wm + mi * 16 + g + half * 8;
                float v0 = acc[mi][ni][half * 2 + 0];
                float v1 = acc[mi][ni][half * 2 + 1];
                if (out_bf16) {
                    __nv_bfloat162* cp =
                        (__nv_bfloat162*)((__nv_bfloat16*)Cv + (size_t)row * ldc + col);
                    *cp = __float22bfloat162_rn(make_float2(v0, v1));
                    continue;
                }
                float* C = (float*)Cv;
                if (bias0) { v0 += bias0[col]; v1 += bias0[col + 1]; }
                if (bias1) { v0 += bias1[col]; v1 += bias1[col + 1]; }
                if (Cin) {
                    float2 ci = *(const float2*)(Cin + (size_t)row * ldcin + col);
                    v0 += ci.x; v1 += ci.y;
                }
                float2* cp = (float2*)(C + (size_t)row * ldc + col);
                if (accumulate) {
                    float2 c = *cp;
                    v0 += c.x; v1 += c.y;
                }
                *cp = make_float2(v0, v1);
            }
        }
    }
}

template <int BM, int BN, int BK, int WM, int WN>
static void mgemm(int M, int N, int K,
                  const float* A, int lda, const float* B, int ldb,
                  void* C, int ldc,
                  const float* Cin = nullptr, int ldcin = 0,
                  const float* bias0 = nullptr, const float* bias1 = nullptr,
                  bool accumulate = false, bool out_bf16 = false) {
    dim3 grid(N / BN, M / BM);
    mma_nt_kernel<BM, BN, BK, WM, WN><<<grid, (BM / WM) * (BN / WN) * 32>>>(
        M, N, K, A, lda, B, ldb, C, ldc, Cin, ldcin, bias0, bias1,
        accumulate ? 1 : 0, out_bf16 ? 1 : 0);
}

// ---------------- precompute kernels ----------------
__global__ void embed_kernel(const int* __restrict__ targets,
                             const float* __restrict__ emb,
                             float* __restrict__ xemb) {
    int idx = blockIdx.x * blockDim.x + threadIdx.x;  // B*T*E
    int e = idx & (EE - 1);
    int m = idx >> 8;        // b*T + t
    int t = m & (TT - 1);
    int b = m >> 5;
    int tok = (t == 0) ? EOS_IDX : targets[b * TT + t - 1];
    xemb[idx] = emb[(size_t)tok * EE + e];
}

__global__ void build_wcomb_kernel(const float* __restrict__ W_ih0,
                                   const float* __restrict__ W_hh0,
                                   const float* __restrict__ W_ih1,
                                   const float* __restrict__ W_hh1,
                                   float* __restrict__ Wc0,
                                   float* __restrict__ Wc1) {
    int idx = blockIdx.x * blockDim.x + threadIdx.x;
    const int N0 = G4H * (DENC + HH);
    const int N1 = G4H * (HH + HH);
    if (idx < N0) {
        int n = idx / (DENC + HH);
        int k = idx % (DENC + HH);
        Wc0[idx] = (k < DENC) ? W_ih0[(size_t)n * (EE + DENC) + EE + k]
                              : W_hh0[(size_t)n * HH + (k - DENC)];
    } else if (idx < N0 + N1) {
        int r = idx - N0;
        int n = r / (HH + HH);
        int k = r % (HH + HH);
        Wc1[r] = (k < HH) ? W_ih1[(size_t)n * HH + k]
                          : W_hh1[(size_t)n * HH + (k - HH)];
    }
}

__global__ void init_state_kernel(const float* __restrict__ h0,
                                  const float* __restrict__ c0,
                                  float* __restrict__ xbuf,
                                  float* __restrict__ x1buf,
                                  float* __restrict__ cb0,
                                  float* __restrict__ cb1) {
    int idx = blockIdx.x * blockDim.x + threadIdx.x;  // B*H
    int b = idx >> 9;
    int h = idx & (HH - 1);
    xbuf[(size_t)b * (DENC + HH) + DENC + h] = h0[idx];                 // layer 0 h
    x1buf[(size_t)b * (HH + HH) + HH + h] = h0[(size_t)BB * HH + idx];  // layer 1 h
    cb0[idx] = c0[idx];
    cb1[idx] = c0[(size_t)BB * HH + idx];
}

// ---------------- attention (fused score/tanh + masked softmax + context) ----------------
__global__ void __launch_bounds__(256) attention_kernel(
    const __nv_bfloat16* __restrict__ enc_proj,   // (B,S,H) bf16
    const float* __restrict__ enc,        // (B,S,DENC) fp32
    const float* __restrict__ decp,       // (B,H)
    const float* __restrict__ vvec,       // (H)
    const int* __restrict__ mask,         // (B,S)
    float* __restrict__ ctx_dst1, int ld1,  // xbuf: col 0
    float* __restrict__ ctx_dst2, int ld2)  // pred slice (already offset by H)
{
    const int b = blockIdx.x;
    __shared__ float s_dp[HH];
    __shared__ float s_v[HH];
    __shared__ float s_w[SS];
    __shared__ float s_red[2];
    const int tid = threadIdx.x;
    const int warp = tid >> 5, lane = tid & 31;

    for (int i = tid; i < HH; i += 256) {
        s_dp[i] = decp[(size_t)b * HH + i];
        s_v[i] = vvec[i];
    }
    __syncthreads();

    for (int s = warp; s < SS; s += 8) {
        const __nv_bfloat162* ep =
            (const __nv_bfloat162*)(enc_proj + ((size_t)b * SS + s) * HH);
        float acc = 0.0f;
#pragma unroll 4
        for (int h2 = lane; h2 < HH / 2; h2 += 32) {
            float2 e = __bfloat1622float2(ep[h2]);
            acc += s_v[2 * h2] * tanhf(s_dp[2 * h2] + e.x);
            acc += s_v[2 * h2 + 1] * tanhf(s_dp[2 * h2 + 1] + e.y);
        }
#pragma unroll
        for (int o = 16; o; o >>= 1) acc += __shfl_xor_sync(0xffffffffu, acc, o);
        if (lane == 0) s_w[s] = mask[b * SS + s] ? acc : -1e30f;
    }
    __syncthreads();

    if (warp == 0) {
        float m = fmaxf(s_w[lane], s_w[lane + 32]);
#pragma unroll
        for (int o = 16; o; o >>= 1) m = fmaxf(m, __shfl_xor_sync(0xffffffffu, m, o));
        float sum = expf(s_w[lane] - m) + expf(s_w[lane + 32] - m);
#pragma unroll
        for (int o = 16; o; o >>= 1) sum += __shfl_xor_sync(0xffffffffu, sum, o);
        if (lane == 0) { s_red[0] = m; s_red[1] = sum; }
    }
    __syncthreads();
    const float m = s_red[0], inv = 1.0f / s_red[1];
    if (tid < SS) s_w[tid] = expf(s_w[tid] - m) * inv;
    __syncthreads();

    const float* eb = enc + (size_t)b * SS * DENC;
    for (int d = tid; d < DENC; d += 256) {
        float acc = 0.0f;
#pragma unroll 8
        for (int s = 0; s < SS; s++) acc += s_w[s] * eb[(size_t)s * DENC + d];
        ctx_dst1[(size_t)b * ld1 + d] = acc;
        ctx_dst2[(size_t)b * ld2 + d] = acc;
    }
}

// ---------------- LSTM pointwise cell ----------------
__global__ void lstm_cell_kernel(const float* __restrict__ gates,  // (B,4H)
                                 float* __restrict__ c,            // (B,H) in/out
                                 float* __restrict__ hA, int ldA,
                                 float* __restrict__ hB, int ldB) {
    int idx = blockIdx.x * blockDim.x + threadIdx.x;  // B*H
    int b = idx >> 9;
    int h = idx & (HH - 1);
    const float* g = gates + (size_t)b * G4H;
    float ig = sigmoidf_(g[h]);
    float fg = sigmoidf_(g[HH + h]);
    float gg = tanhf(g[2 * HH + h]);
    float og = sigmoidf_(g[3 * HH + h]);
    float cn = fg * c[idx] + ig * gg;
    c[idx] = cn;
    float hn = og * tanhf(cn);
    hA[(size_t)b * ldA + h] = hn;
    hB[(size_t)b * ldB + h] = hn;
}

// ---------------- host ----------------
extern "C" void kernel_launch(void* const* d_in, const int* in_sizes, int n_in,
                              void* d_out, int out_size) {
    const float* encoder_out = (const float*)d_in[0];
    const float* h0   = (const float*)d_in[1];
    const float* c0   = (const float*)d_in[2];
    const int*   targets = (const int*)d_in[3];
    const int*   mask    = (const int*)d_in[4];
    const float* emb   = (const float*)d_in[5];
    const float* W_enc = (const float*)d_in[6];
    const float* W_dec = (const float*)d_in[7];
    const float* vvec  = (const float*)d_in[8];
    const float* W_ih0 = (const float*)d_in[9];
    const float* W_hh0 = (const float*)d_in[10];
    const float* b_ih0 = (const float*)d_in[11];
    const float* b_hh0 = (const float*)d_in[12];
    const float* W_ih1 = (const float*)d_in[13];
    const float* W_hh1 = (const float*)d_in[14];
    const float* b_ih1 = (const float*)d_in[15];
    const float* b_hh1 = (const float*)d_in[16];
    const float* W_out = (const float*)d_in[17];
    const float* b_out = (const float*)d_in[18];
    float* out = (float*)d_out;  // (B,T,V)

    __nv_bfloat16* p_encproj_bf;
    float *p_xemb, *p_gates_emb, *p_pred, *p_Wc0, *p_Wc1;
    float *p_xbuf, *p_x1buf, *p_gates, *p_c0, *p_c1, *p_decproj;
    cudaGetSymbolAddress((void**)&p_encproj_bf, g_encproj_bf);
    cudaGetSymbolAddress((void**)&p_xemb, g_xemb);
    cudaGetSymbolAddress((void**)&p_gates_emb, g_gates_emb);
    cudaGetSymbolAddress((void**)&p_pred, g_pred);
    cudaGetSymbolAddress((void**)&p_Wc0, g_Wc0);
    cudaGetSymbolAddress((void**)&p_Wc1, g_Wc1);
    cudaGetSymbolAddress((void**)&p_xbuf, g_xbuf);
    cudaGetSymbolAddress((void**)&p_x1buf, g_x1buf);
    cudaGetSymbolAddress((void**)&p_gates, g_gates);
    cudaGetSymbolAddress((void**)&p_c0, g_c0buf);
    cudaGetSymbolAddress((void**)&p_c1, g_c1buf);
    cudaGetSymbolAddress((void**)&p_decproj, g_decproj);

    // ---- precompute (parallel over all timesteps) ----
    embed_kernel<<<(BB * TT * EE) / 256, 256>>>(targets, emb, p_xemb);
    {
        int total = G4H * (DENC + HH) + G4H * (HH + HH);
        build_wcomb_kernel<<<(total + 255) / 256, 256>>>(W_ih0, W_hh0, W_ih1, W_hh1, p_Wc0, p_Wc1);
    }
    init_state_kernel<<<(BB * HH) / 256, 256>>>(h0, c0, p_xbuf, p_x1buf, p_c0, p_c1);

    // enc_proj (B*S, H) = encoder_out (B*S, DENC) @ W_enc^T  -> bf16 (score path only)
    mgemm<128, 128, 16, 64, 32>(BB * SS, HH, DENC, encoder_out, DENC, W_enc, DENC,
                                p_encproj_bf, HH, nullptr, 0, nullptr, nullptr,
                                false, /*out_bf16=*/true);
    // gates_emb (B*T, 4H) = x_emb @ W_ih0[:, :E]^T
    mgemm<128, 128, 16, 64, 32>(BB * TT, G4H, EE, p_xemb, EE, W_ih0, EE + DENC,
                                p_gates_emb, G4H);
    // pred_emb -> out directly: (B*T, V) = x_emb @ W_out[:, H+DENC:]^T + b_out
    mgemm<128, 128, 16, 64, 32>(BB * TT, VV, EE, p_xemb, EE, W_out + (HH + DENC),
                                HH + DENC + EE, out, VV, nullptr, 0, b_out, nullptr, false);

    // ---- sequential decode ----
    for (int t = 0; t < TT; t++) {
        // dec_proj = h1 @ W_dec^T   (h1 lives in x1buf cols [H, 2H))
        mgemm<64, 64, 16, 32, 32>(BB, HH, HH, p_x1buf + HH, HH + HH, W_dec, HH,
                                  p_decproj, HH);

        // attention: context -> xbuf[:, :DENC] and pred[:, t, H:]
        attention_kernel<<<BB, 256>>>(p_encproj_bf, encoder_out, p_decproj, vvec, mask,
                                      p_xbuf, DENC + HH,
                                      p_pred + (size_t)t * PCOL + HH, TT * PCOL);

        // gates0 = [context|h0] @ Wc0^T + gates_emb[:,t,:] + b_ih0 + b_hh0
        mgemm<64, 128, 16, 32, 64>(BB, G4H, DENC + HH, p_xbuf, DENC + HH, p_Wc0, DENC + HH,
                                   p_gates, G4H, p_gates_emb + (size_t)t * G4H, TT * G4H,
                                   b_ih0, b_hh0, false);
        lstm_cell_kernel<<<(BB * HH) / 256, 256>>>(p_gates, p_c0,
                                                   p_x1buf, HH + HH,           // h0n -> x1buf[:, :H]
                                                   p_xbuf + DENC, DENC + HH);  // h0n -> xbuf[:, DENC:]

        // gates1 = [h0n|h1] @ Wc1^T + b_ih1 + b_hh1
        mgemm<64, 128, 16, 32, 64>(BB, G4H, HH + HH, p_x1buf, HH + HH, p_Wc1, HH + HH,
                                   p_gates, G4H, nullptr, 0, b_ih1, b_hh1, false);
        lstm_cell_kernel<<<(BB * HH) / 256, 256>>>(p_gates, p_c1,
                                                   p_x1buf + HH, HH + HH,       // h1n -> x1buf[:, H:]
                                                   p_pred + (size_t)t * PCOL, TT * PCOL); // h1n -> pred[:, t, :H]
    }

    // pred logits: out += [h1n|context]_(B*T,1536) @ W_out[:, :H+DENC]^T
    mgemm<128, 128, 16, 64, 32>(BB * TT, VV, PCOL, p_pred, PCOL, W_out, HH + DENC + EE,
                                out, VV, nullptr, 0, nullptr, nullptr, true);
}